// round 2
// baseline (speedup 1.0000x reference)
#include <cuda_runtime.h>
#include <cuda_bf16.h>
#include <cstdint>

// Problem constants
#define Bb     2
#define Sq     2048
#define Dd     512
#define Hh     8
#define BHh    16
#define Mrows  4096     // Bb*Sq
#define HDc    4096     // Hh*Dd
#define SCALE  0.04419417382415922f   // 1/sqrt(512)

// Scratch (static __device__ — allocation-guard safe)
__device__ float g_Q[(size_t)BHh * Sq * Dd];           // 64 MB  [bh][s][e]
__device__ float g_K[(size_t)BHh * Sq * Dd];           // 64 MB
__device__ float g_V[(size_t)BHh * Sq * Dd];           // 64 MB
__device__ float g_S[(size_t)BHh * Sq * Sq];           // 256 MB [bh][q][k]
__device__ float g_C[(size_t)Mrows * HDc];             // 64 MB  concat [b*S+s][h*D+e]

// ---------------------------------------------------------------------------
// TF32 mma.sync GEMM: 128x128 tile, BK=32, 256 threads (8 warps).
// Warp grid 4(M) x 2(N); warp tile 32x64 = 2 x 8 fragments of m16n8k8.
// MODE 0: QKV projection   C = X @ W{q,k,v}[h] + bias      (z = t*8+h)
// MODE 1: scores           C = Q_bh @ K_bh^T * scale       (z = bh)
// MODE 2: P@V              C = S_bh @ V_bh -> concat layout (z = bh)
// MODE 3: out projection   C = concat @ Wo + bo + x -> d_out
// All dims divide tile sizes exactly -> no bounds guards.
// ---------------------------------------------------------------------------
#define BM 128
#define BN 128
#define BK 32
#define AS_LD 36      // BK + 4 pad (floats)
#define BS_LD 132     // BN + 4 pad (floats)

__device__ __forceinline__ uint32_t f2tf32(float f) {
    uint32_t r;
    asm("cvt.rna.tf32.f32 %0, %1;" : "=r"(r) : "f"(f));
    return r;
}

__device__ __forceinline__ void mma_tf32(float* d, const uint32_t* a, const uint32_t* b) {
    asm volatile(
        "mma.sync.aligned.m16n8k8.row.col.f32.tf32.tf32.f32 "
        "{%0,%1,%2,%3}, {%4,%5,%6,%7}, {%8,%9}, {%0,%1,%2,%3};"
        : "+f"(d[0]), "+f"(d[1]), "+f"(d[2]), "+f"(d[3])
        : "r"(a[0]), "r"(a[1]), "r"(a[2]), "r"(a[3]), "r"(b[0]), "r"(b[1]));
}

template <int MODE>
__global__ void __launch_bounds__(256, 2) gemm_k(
    const float* __restrict__ X,
    const float* __restrict__ Wq, const float* __restrict__ Wk,
    const float* __restrict__ Wv,
    const float* __restrict__ bq, const float* __restrict__ bk,
    const float* __restrict__ bv,
    const float* __restrict__ Wo, const float* __restrict__ bo,
    float* __restrict__ OUT)
{
    __shared__ uint32_t As[BM * AS_LD];   // [m][k] row-major, padded
    __shared__ uint32_t Bs[BK * BS_LD];   // [k][n] row-major, padded

    const int tid  = threadIdx.x;
    const int lane = tid & 31;
    const int warp = tid >> 5;
    const int wm   = warp & 3;            // 0..3  (32 rows each)
    const int wn   = warp >> 2;           // 0..1  (64 cols each)
    const int gid  = lane >> 2;           // 0..7
    const int tig  = lane & 3;            // 0..3

    const int n0 = blockIdx.x * BN;
    const int m0 = blockIdx.y * BM;
    const int z  = blockIdx.z;

    const float* Aptr;
    const float* Bptr;
    int lda, Kdim;

    if (MODE == 0) {
        const int t = z >> 3, h = z & 7;
        Aptr = X;  lda = Dd;  Kdim = Dd;
        Bptr = (t == 0 ? Wq : (t == 1 ? Wk : Wv)) + (size_t)h * Dd * Dd;
    } else if (MODE == 1) {
        Aptr = g_Q + (size_t)z * Sq * Dd;  lda = Dd;  Kdim = Dd;
        Bptr = g_K + (size_t)z * Sq * Dd;              // transposed access
    } else if (MODE == 2) {
        Aptr = g_S + (size_t)z * Sq * Sq;  lda = Sq;  Kdim = Sq;
        Bptr = g_V + (size_t)z * Sq * Dd;
    } else {
        Aptr = g_C;  lda = HDc;  Kdim = HDc;
        Bptr = Wo;
    }
    const int ldb = Dd;   // every B matrix has leading dim 512

    // A gmem->smem mapping: 128 rows x 8 float4; thread t covers row t/2,
    // vec-cols (t&1)*4 + i
    const int a_r  = tid >> 1;
    const int a_v0 = (tid & 1) * 4;
    // B normal mapping: 32 k-rows x 32 float4; thread t covers k-row t/8,
    // vec-cols (t&7)*4 + i
    const int b_k  = tid >> 3;
    const int b_v0 = (tid & 7) * 4;
    // B transposed mapping (MODE 1): n-row t/2, k-vecs (t&1)*4 + i
    const int bt_n  = tid >> 1;
    const int bt_v0 = (tid & 1) * 4;

    float acc[2][8][4];
#pragma unroll
    for (int mi = 0; mi < 2; mi++)
#pragma unroll
        for (int nj = 0; nj < 8; nj++)
#pragma unroll
            for (int e = 0; e < 4; e++) acc[mi][nj][e] = 0.0f;

    for (int k0 = 0; k0 < Kdim; k0 += BK) {
        // ---- A tile ----
#pragma unroll
        for (int i = 0; i < 4; i++) {
            const int v = a_v0 + i;                 // 0..7
            const float4 av = *(const float4*)(Aptr + (size_t)(m0 + a_r) * lda + k0 + v * 4);
            uint32_t* dst = &As[a_r * AS_LD + v * 4];
            dst[0] = f2tf32(av.x); dst[1] = f2tf32(av.y);
            dst[2] = f2tf32(av.z); dst[3] = f2tf32(av.w);
        }
        // ---- B tile ----
        if (MODE == 1) {
#pragma unroll
            for (int i = 0; i < 4; i++) {
                const int v = bt_v0 + i;            // 0..7, covers k 4v..4v+3
                const float4 bv4 = *(const float4*)(Bptr + (size_t)(n0 + bt_n) * ldb + k0 + v * 4);
                Bs[(v * 4 + 0) * BS_LD + bt_n] = f2tf32(bv4.x);
                Bs[(v * 4 + 1) * BS_LD + bt_n] = f2tf32(bv4.y);
                Bs[(v * 4 + 2) * BS_LD + bt_n] = f2tf32(bv4.z);
                Bs[(v * 4 + 3) * BS_LD + bt_n] = f2tf32(bv4.w);
            }
        } else {
#pragma unroll
            for (int i = 0; i < 4; i++) {
                const int v = b_v0 + i;             // 0..31
                const float4 bv4 = *(const float4*)(Bptr + (size_t)(k0 + b_k) * ldb + n0 + v * 4);
                uint32_t* dst = &Bs[b_k * BS_LD + v * 4];
                dst[0] = f2tf32(bv4.x); dst[1] = f2tf32(bv4.y);
                dst[2] = f2tf32(bv4.z); dst[3] = f2tf32(bv4.w);
            }
        }
        __syncthreads();

#pragma unroll
        for (int ks = 0; ks < BK / 8; ks++) {
            const int kb = ks * 8;
            uint32_t a[2][4];
#pragma unroll
            for (int mi = 0; mi < 2; mi++) {
                const int r = wm * 32 + mi * 16 + gid;
                a[mi][0] = As[r * AS_LD + kb + tig];
                a[mi][1] = As[(r + 8) * AS_LD + kb + tig];
                a[mi][2] = As[r * AS_LD + kb + tig + 4];
                a[mi][3] = As[(r + 8) * AS_LD + kb + tig + 4];
            }
            uint32_t b[8][2];
#pragma unroll
            for (int nj = 0; nj < 8; nj++) {
                const int c = wn * 64 + nj * 8 + gid;
                b[nj][0] = Bs[(kb + tig) * BS_LD + c];
                b[nj][1] = Bs[(kb + tig + 4) * BS_LD + c];
            }
#pragma unroll
            for (int mi = 0; mi < 2; mi++)
#pragma unroll
                for (int nj = 0; nj < 8; nj++)
                    mma_tf32(acc[mi][nj], a[mi], b[nj]);
        }
        __syncthreads();
    }

    // ---- epilogue ----
    // fragment (mi,nj): rows rr0 = wm*32+mi*16+gid, rr1 = rr0+8 (block-relative)
    //                   cols cc0 = wn*64+nj*8+2*tig, cc1 = cc0+1
#pragma unroll
    for (int mi = 0; mi < 2; mi++) {
#pragma unroll
        for (int nj = 0; nj < 8; nj++) {
            const int rr0 = wm * 32 + mi * 16 + gid;
            const int rr1 = rr0 + 8;
            const int cc0 = wn * 64 + nj * 8 + 2 * tig;
            const float* a4 = acc[mi][nj];

            if (MODE == 0) {
                const int t = z >> 3, h = z & 7;
                const float* bias = (t == 0 ? bq : (t == 1 ? bk : bv)) + h * Dd;
                float* Cb = (t == 0 ? g_Q : (t == 1 ? g_K : g_V));
                const int b = m0 >> 11;
                const int sb = (m0 & (Sq - 1));
                float* Cp = Cb + (size_t)(b * Hh + h) * Sq * Dd;
                const int c0 = n0 + cc0;
                const float bias0 = bias[c0], bias1 = bias[c0 + 1];
                Cp[(size_t)(sb + rr0) * Dd + c0]     = a4[0] + bias0;
                Cp[(size_t)(sb + rr0) * Dd + c0 + 1] = a4[1] + bias1;
                Cp[(size_t)(sb + rr1) * Dd + c0]     = a4[2] + bias0;
                Cp[(size_t)(sb + rr1) * Dd + c0 + 1] = a4[3] + bias1;
            } else if (MODE == 1) {
                float* Cp = g_S + (size_t)z * Sq * Sq;
                const int c0 = n0 + cc0;
                Cp[(size_t)(m0 + rr0) * Sq + c0]     = a4[0] * SCALE;
                Cp[(size_t)(m0 + rr0) * Sq + c0 + 1] = a4[1] * SCALE;
                Cp[(size_t)(m0 + rr1) * Sq + c0]     = a4[2] * SCALE;
                Cp[(size_t)(m0 + rr1) * Sq + c0 + 1] = a4[3] * SCALE;
            } else if (MODE == 2) {
                const int b = z >> 3, h = z & 7;
                const int c0 = h * Dd + n0 + cc0;
                g_C[(size_t)(b * Sq + m0 + rr0) * HDc + c0]     = a4[0];
                g_C[(size_t)(b * Sq + m0 + rr0) * HDc + c0 + 1] = a4[1];
                g_C[(size_t)(b * Sq + m0 + rr1) * HDc + c0]     = a4[2];
                g_C[(size_t)(b * Sq + m0 + rr1) * HDc + c0 + 1] = a4[3];
            } else {
                const int r0 = m0 + rr0, r1 = m0 + rr1;
                const int c0 = n0 + cc0;
                const float bo0 = bo[c0], bo1 = bo[c0 + 1];
                OUT[(size_t)r0 * Dd + c0]     = a4[0] + bo0 + X[(size_t)r0 * Dd + c0];
                OUT[(size_t)r0 * Dd + c0 + 1] = a4[1] + bo1 + X[(size_t)r0 * Dd + c0 + 1];
                OUT[(size_t)r1 * Dd + c0]     = a4[2] + bo0 + X[(size_t)r1 * Dd + c0];
                OUT[(size_t)r1 * Dd + c0 + 1] = a4[3] + bo1 + X[(size_t)r1 * Dd + c0 + 1];
            }
        }
    }
}

// ---------------------------------------------------------------------------
// Row softmax over g_S: 32768 rows x 2048 cols, one 256-thread block per row.
// ---------------------------------------------------------------------------
__global__ void __launch_bounds__(256) softmax_k()
{
    const int row = blockIdx.x;
    float* p = g_S + (size_t)row * Sq;
    const int tid = threadIdx.x;

    float v[8];
    float mx = -1e30f;
#pragma unroll
    for (int i = 0; i < 8; i++) {
        v[i] = p[tid + i * 256];
        mx = fmaxf(mx, v[i]);
    }
#pragma unroll
    for (int o = 16; o; o >>= 1) mx = fmaxf(mx, __shfl_xor_sync(0xFFFFFFFFu, mx, o));

    __shared__ float red[8];
    const int w = tid >> 5, l = tid & 31;
    if (l == 0) red[w] = mx;
    __syncthreads();
    float m = red[0];
#pragma unroll
    for (int i = 1; i < 8; i++) m = fmaxf(m, red[i]);
    __syncthreads();

    float s = 0.0f;
#pragma unroll
    for (int i = 0; i < 8; i++) {
        v[i] = __expf(v[i] - m);
        s += v[i];
    }
#pragma unroll
    for (int o = 16; o; o >>= 1) s += __shfl_xor_sync(0xFFFFFFFFu, s, o);
    if (l == 0) red[w] = s;
    __syncthreads();
    float tot = 0.0f;
#pragma unroll
    for (int i = 0; i < 8; i++) tot += red[i];
    const float inv = __frcp_rn(tot);

#pragma unroll
    for (int i = 0; i < 8; i++) p[tid + i * 256] = v[i] * inv;
}

// ---------------------------------------------------------------------------
extern "C" void kernel_launch(void* const* d_in, const int* in_sizes, int n_in,
                              void* d_out, int out_size)
{
    (void)in_sizes; (void)n_in; (void)out_size;
    const float* x  = (const float*)d_in[0];
    const float* Wq = (const float*)d_in[1];
    const float* Wk = (const float*)d_in[2];
    const float* Wv = (const float*)d_in[3];
    const float* bq = (const float*)d_in[4];
    const float* bk = (const float*)d_in[5];
    const float* bv = (const float*)d_in[6];
    const float* Wo = (const float*)d_in[7];
    const float* bo = (const float*)d_in[8];
    float* out = (float*)d_out;

    // 1) QKV projections: 24 GEMMs of [4096,512]x[512,512]
    gemm_k<0><<<dim3(Dd / BN, Mrows / BM, 24), 256>>>(x, Wq, Wk, Wv, bq, bk, bv, Wo, bo, out);
    // 2) Scores: 16 GEMMs of [2048,2048,512], scaled
    gemm_k<1><<<dim3(Sq / BN, Sq / BM, BHh), 256>>>(x, Wq, Wk, Wv, bq, bk, bv, Wo, bo, out);
    // 3) Row softmax
    softmax_k<<<BHh * Sq, 256>>>();
    // 4) P @ V -> concat layout: 16 GEMMs of [2048,512,2048]
    gemm_k<2><<<dim3(Dd / BN, Sq / BM, BHh), 256>>>(x, Wq, Wk, Wv, bq, bk, bv, Wo, bo, out);
    // 5) Output projection + bias + residual: [4096,512,4096]
    gemm_k<3><<<dim3(Dd / BN, Mrows / BM, 1), 256>>>(x, Wq, Wk, Wv, bq, bk, bv, Wo, bo, out);
}

// round 4
// speedup vs baseline: 1.1145x; 1.1145x over previous
#include <cuda_runtime.h>
#include <cuda_bf16.h>
#include <cstdint>

// Problem constants
#define Bb     2
#define Sq     2048
#define Dd     512
#define Hh     8
#define BHh    16
#define Mrows  4096     // Bb*Sq
#define HDc    4096     // Hh*Dd
#define SCALE  0.04419417382415922f   // 1/sqrt(512)

// Scratch (static __device__ — allocation-guard safe)
__device__ float g_Q[(size_t)BHh * Sq * Dd];           // 64 MB  [bh][s][e]
__device__ float g_K[(size_t)BHh * Sq * Dd];           // 64 MB
__device__ float g_V[(size_t)BHh * Sq * Dd];           // 64 MB
__device__ float g_S[(size_t)BHh * Sq * Sq];           // 256 MB [bh][q][k]
__device__ float g_C[(size_t)Mrows * HDc];             // 64 MB  concat [b*S+s][h*D+e]

// ---------------------------------------------------------------------------
// TF32 mma.sync GEMM: 128x128 tile, BK=32, 256 threads (8 warps).
// Warp grid 4(M) x 2(N); warp tile 32x64 = 2 x 8 fragments of m16n8k8.
// MODE 0: QKV projection   C = X @ W{q,k,v}[h] + bias      (z = t*8+h)
// MODE 1: scores           C = Q_bh @ K_bh^T * scale       (z = bh)
// MODE 2: P@V              C = S_bh @ V_bh -> concat layout (z = bh)
// MODE 3: out projection   C = concat @ Wo + bo + x -> d_out
// All dims divide tile sizes exactly -> no bounds guards.
//
// R3: BS_LD 132 -> 136. With 132 (mod 32 = 4) the B fragment loads hit
// 2-way bank conflicts (bank = tig*4+gid collides across (tig,gid) pairs).
// With 136 (mod 32 = 8) bank = tig*8+gid, bijective over 32 lanes ->
// conflict-free. Removes 16 excess wavefronts per ks-step per warp
// (40 -> 24 = byte floor for this fragment shape).
// ---------------------------------------------------------------------------
#define BM 128
#define BN 128
#define BK 32
#define AS_LD 36      // BK + 4 pad (floats): frag-read bank = gid*4+tig, conflict-free
#define BS_LD 136     // BN + 8 pad (floats): frag-read bank = tig*8+gid, conflict-free

__device__ __forceinline__ uint32_t f2tf32(float f) {
    uint32_t r;
    asm("cvt.rna.tf32.f32 %0, %1;" : "=r"(r) : "f"(f));
    return r;
}

__device__ __forceinline__ void mma_tf32(float* d, const uint32_t* a, const uint32_t* b) {
    asm volatile(
        "mma.sync.aligned.m16n8k8.row.col.f32.tf32.tf32.f32 "
        "{%0,%1,%2,%3}, {%4,%5,%6,%7}, {%8,%9}, {%0,%1,%2,%3};"
        : "+f"(d[0]), "+f"(d[1]), "+f"(d[2]), "+f"(d[3])
        : "r"(a[0]), "r"(a[1]), "r"(a[2]), "r"(a[3]), "r"(b[0]), "r"(b[1]));
}

template <int MODE>
__global__ void __launch_bounds__(256, 2) gemm_k(
    const float* __restrict__ X,
    const float* __restrict__ Wq, const float* __restrict__ Wk,
    const float* __restrict__ Wv,
    const float* __restrict__ bq, const float* __restrict__ bk,
    const float* __restrict__ bv,
    const float* __restrict__ Wo, const float* __restrict__ bo,
    float* __restrict__ OUT)
{
    __shared__ uint32_t As[BM * AS_LD];   // [m][k] row-major, padded
    __shared__ uint32_t Bs[BK * BS_LD];   // [k][n] row-major, padded

    const int tid  = threadIdx.x;
    const int lane = tid & 31;
    const int warp = tid >> 5;
    const int wm   = warp & 3;            // 0..3  (32 rows each)
    const int wn   = warp >> 2;           // 0..1  (64 cols each)
    const int gid  = lane >> 2;           // 0..7
    const int tig  = lane & 3;            // 0..3

    const int n0 = blockIdx.x * BN;
    const int m0 = blockIdx.y * BM;
    const int z  = blockIdx.z;

    const float* Aptr;
    const float* Bptr;
    int lda, Kdim;

    if (MODE == 0) {
        const int t = z >> 3, h = z & 7;
        Aptr = X;  lda = Dd;  Kdim = Dd;
        Bptr = (t == 0 ? Wq : (t == 1 ? Wk : Wv)) + (size_t)h * Dd * Dd;
    } else if (MODE == 1) {
        Aptr = g_Q + (size_t)z * Sq * Dd;  lda = Dd;  Kdim = Dd;
        Bptr = g_K + (size_t)z * Sq * Dd;              // transposed access
    } else if (MODE == 2) {
        Aptr = g_S + (size_t)z * Sq * Sq;  lda = Sq;  Kdim = Sq;
        Bptr = g_V + (size_t)z * Sq * Dd;
    } else {
        Aptr = g_C;  lda = HDc;  Kdim = HDc;
        Bptr = Wo;
    }
    const int ldb = Dd;   // every B matrix has leading dim 512

    // A gmem->smem mapping: 128 rows x 8 float4; thread t covers row t/2,
    // vec-cols (t&1)*4 + i
    const int a_r  = tid >> 1;
    const int a_v0 = (tid & 1) * 4;
    // B normal mapping: 32 k-rows x 32 float4; thread t covers k-row t/8,
    // vec-cols (t&7)*4 + i
    const int b_k  = tid >> 3;
    const int b_v0 = (tid & 7) * 4;
    // B transposed mapping (MODE 1): n-row t/2, k-vecs (t&1)*4 + i
    const int bt_n  = tid >> 1;
    const int bt_v0 = (tid & 1) * 4;

    float acc[2][8][4];
#pragma unroll
    for (int mi = 0; mi < 2; mi++)
#pragma unroll
        for (int nj = 0; nj < 8; nj++)
#pragma unroll
            for (int e = 0; e < 4; e++) acc[mi][nj][e] = 0.0f;

    for (int k0 = 0; k0 < Kdim; k0 += BK) {
        // ---- A tile ----
#pragma unroll
        for (int i = 0; i < 4; i++) {
            const int v = a_v0 + i;                 // 0..7
            const float4 av = *(const float4*)(Aptr + (size_t)(m0 + a_r) * lda + k0 + v * 4);
            uint32_t* dst = &As[a_r * AS_LD + v * 4];
            dst[0] = f2tf32(av.x); dst[1] = f2tf32(av.y);
            dst[2] = f2tf32(av.z); dst[3] = f2tf32(av.w);
        }
        // ---- B tile ----
        if (MODE == 1) {
#pragma unroll
            for (int i = 0; i < 4; i++) {
                const int v = bt_v0 + i;            // 0..7, covers k 4v..4v+3
                const float4 bv4 = *(const float4*)(Bptr + (size_t)(n0 + bt_n) * ldb + k0 + v * 4);
                Bs[(v * 4 + 0) * BS_LD + bt_n] = f2tf32(bv4.x);
                Bs[(v * 4 + 1) * BS_LD + bt_n] = f2tf32(bv4.y);
                Bs[(v * 4 + 2) * BS_LD + bt_n] = f2tf32(bv4.z);
                Bs[(v * 4 + 3) * BS_LD + bt_n] = f2tf32(bv4.w);
            }
        } else {
#pragma unroll
            for (int i = 0; i < 4; i++) {
                const int v = b_v0 + i;             // 0..31
                const float4 bv4 = *(const float4*)(Bptr + (size_t)(k0 + b_k) * ldb + n0 + v * 4);
                uint32_t* dst = &Bs[b_k * BS_LD + v * 4];
                dst[0] = f2tf32(bv4.x); dst[1] = f2tf32(bv4.y);
                dst[2] = f2tf32(bv4.z); dst[3] = f2tf32(bv4.w);
            }
        }
        __syncthreads();

#pragma unroll
        for (int ks = 0; ks < BK / 8; ks++) {
            const int kb = ks * 8;
            uint32_t a[2][4];
#pragma unroll
            for (int mi = 0; mi < 2; mi++) {
                const int r = wm * 32 + mi * 16 + gid;
                a[mi][0] = As[r * AS_LD + kb + tig];
                a[mi][1] = As[(r + 8) * AS_LD + kb + tig];
                a[mi][2] = As[r * AS_LD + kb + tig + 4];
                a[mi][3] = As[(r + 8) * AS_LD + kb + tig + 4];
            }
            uint32_t b[8][2];
#pragma unroll
            for (int nj = 0; nj < 8; nj++) {
                const int c = wn * 64 + nj * 8 + gid;
                b[nj][0] = Bs[(kb + tig) * BS_LD + c];
                b[nj][1] = Bs[(kb + tig + 4) * BS_LD + c];
            }
#pragma unroll
            for (int mi = 0; mi < 2; mi++)
#pragma unroll
                for (int nj = 0; nj < 8; nj++)
                    mma_tf32(acc[mi][nj], a[mi], b[nj]);
        }
        __syncthreads();
    }

    // ---- epilogue ----
    // fragment (mi,nj): rows rr0 = wm*32+mi*16+gid, rr1 = rr0+8 (block-relative)
    //                   cols cc0 = wn*64+nj*8+2*tig, cc1 = cc0+1
#pragma unroll
    for (int mi = 0; mi < 2; mi++) {
#pragma unroll
        for (int nj = 0; nj < 8; nj++) {
            const int rr0 = wm * 32 + mi * 16 + gid;
            const int rr1 = rr0 + 8;
            const int cc0 = wn * 64 + nj * 8 + 2 * tig;
            const float* a4 = acc[mi][nj];

            if (MODE == 0) {
                const int t = z >> 3, h = z & 7;
                const float* bias = (t == 0 ? bq : (t == 1 ? bk : bv)) + h * Dd;
                float* Cb = (t == 0 ? g_Q : (t == 1 ? g_K : g_V));
                const int b = m0 >> 11;
                const int sb = (m0 & (Sq - 1));
                float* Cp = Cb + (size_t)(b * Hh + h) * Sq * Dd;
                const int c0 = n0 + cc0;
                const float bias0 = bias[c0], bias1 = bias[c0 + 1];
                Cp[(size_t)(sb + rr0) * Dd + c0]     = a4[0] + bias0;
                Cp[(size_t)(sb + rr0) * Dd + c0 + 1] = a4[1] + bias1;
                Cp[(size_t)(sb + rr1) * Dd + c0]     = a4[2] + bias0;
                Cp[(size_t)(sb + rr1) * Dd + c0 + 1] = a4[3] + bias1;
            } else if (MODE == 1) {
                float* Cp = g_S + (size_t)z * Sq * Sq;
                const int c0 = n0 + cc0;
                Cp[(size_t)(m0 + rr0) * Sq + c0]     = a4[0] * SCALE;
                Cp[(size_t)(m0 + rr0) * Sq + c0 + 1] = a4[1] * SCALE;
                Cp[(size_t)(m0 + rr1) * Sq + c0]     = a4[2] * SCALE;
                Cp[(size_t)(m0 + rr1) * Sq + c0 + 1] = a4[3] * SCALE;
            } else if (MODE == 2) {
                const int b = z >> 3, h = z & 7;
                const int c0 = h * Dd + n0 + cc0;
                g_C[(size_t)(b * Sq + m0 + rr0) * HDc + c0]     = a4[0];
                g_C[(size_t)(b * Sq + m0 + rr0) * HDc + c0 + 1] = a4[1];
                g_C[(size_t)(b * Sq + m0 + rr1) * HDc + c0]     = a4[2];
                g_C[(size_t)(b * Sq + m0 + rr1) * HDc + c0 + 1] = a4[3];
            } else {
                const int r0 = m0 + rr0, r1 = m0 + rr1;
                const int c0 = n0 + cc0;
                const float bo0 = bo[c0], bo1 = bo[c0 + 1];
                OUT[(size_t)r0 * Dd + c0]     = a4[0] + bo0 + X[(size_t)r0 * Dd + c0];
                OUT[(size_t)r0 * Dd + c0 + 1] = a4[1] + bo1 + X[(size_t)r0 * Dd + c0 + 1];
                OUT[(size_t)r1 * Dd + c0]     = a4[2] + bo0 + X[(size_t)r1 * Dd + c0];
                OUT[(size_t)r1 * Dd + c0 + 1] = a4[3] + bo1 + X[(size_t)r1 * Dd + c0 + 1];
            }
        }
    }
}

// ---------------------------------------------------------------------------
// Row softmax over g_S: 32768 rows x 2048 cols, one 256-thread block per row.
// ---------------------------------------------------------------------------
__global__ void __launch_bounds__(256) softmax_k()
{
    const int row = blockIdx.x;
    float* p = g_S + (size_t)row * Sq;
    const int tid = threadIdx.x;

    float v[8];
    float mx = -1e30f;
#pragma unroll
    for (int i = 0; i < 8; i++) {
        v[i] = p[tid + i * 256];
        mx = fmaxf(mx, v[i]);
    }
#pragma unroll
    for (int o = 16; o; o >>= 1) mx = fmaxf(mx, __shfl_xor_sync(0xFFFFFFFFu, mx, o));

    __shared__ float red[8];
    const int w = tid >> 5, l = tid & 31;
    if (l == 0) red[w] = mx;
    __syncthreads();
    float m = red[0];
#pragma unroll
    for (int i = 1; i < 8; i++) m = fmaxf(m, red[i]);
    __syncthreads();

    float s = 0.0f;
#pragma unroll
    for (int i = 0; i < 8; i++) {
        v[i] = __expf(v[i] - m);
        s += v[i];
    }
#pragma unroll
    for (int o = 16; o; o >>= 1) s += __shfl_xor_sync(0xFFFFFFFFu, s, o);
    if (l == 0) red[w] = s;
    __syncthreads();
    float tot = 0.0f;
#pragma unroll
    for (int i = 0; i < 8; i++) tot += red[i];
    const float inv = __frcp_rn(tot);

#pragma unroll
    for (int i = 0; i < 8; i++) p[tid + i * 256] = v[i] * inv;
}

// ---------------------------------------------------------------------------
extern "C" void kernel_launch(void* const* d_in, const int* in_sizes, int n_in,
                              void* d_out, int out_size)
{
    (void)in_sizes; (void)n_in; (void)out_size;
    const float* x  = (const float*)d_in[0];
    const float* Wq = (const float*)d_in[1];
    const float* Wk = (const float*)d_in[2];
    const float* Wv = (const float*)d_in[3];
    const float* bq = (const float*)d_in[4];
    const float* bk = (const float*)d_in[5];
    const float* bv = (const float*)d_in[6];
    const float* Wo = (const float*)d_in[7];
    const float* bo = (const float*)d_in[8];
    float* out = (float*)d_out;

    // 1) QKV projections: 24 GEMMs of [4096,512]x[512,512]
    gemm_k<0><<<dim3(Dd / BN, Mrows / BM, 24), 256>>>(x, Wq, Wk, Wv, bq, bk, bv, Wo, bo, out);
    // 2) Scores: 16 GEMMs of [2048,2048,512], scaled
    gemm_k<1><<<dim3(Sq / BN, Sq / BM, BHh), 256>>>(x, Wq, Wk, Wv, bq, bk, bv, Wo, bo, out);
    // 3) Row softmax
    softmax_k<<<BHh * Sq, 256>>>();
    // 4) P @ V -> concat layout: 16 GEMMs of [2048,512,2048]
    gemm_k<2><<<dim3(Dd / BN, Sq / BM, BHh), 256>>>(x, Wq, Wk, Wv, bq, bk, bv, Wo, bo, out);
    // 5) Output projection + bias + residual: [4096,512,4096]
    gemm_k<3><<<dim3(Dd / BN, Mrows / BM, 1), 256>>>(x, Wq, Wk, Wv, bq, bk, bv, Wo, bo, out);
}

// round 5
// speedup vs baseline: 1.8398x; 1.6507x over previous
#include <cuda_runtime.h>
#include <cuda_bf16.h>
#include <cstdint>

// Problem constants
#define Bb     2
#define Sq     2048
#define Dd     512
#define Hh     8
#define BHh    16
#define Mrows  4096     // Bb*Sq
#define HDc    4096     // Hh*Dd
#define SCALE  0.04419417382415922f   // 1/sqrt(512)

// Scratch (static __device__ — allocation-guard safe)
__device__ __nv_bfloat16 g_Qb[(size_t)BHh * Sq * Dd];   // 32 MB [bh][s][e]
__device__ __nv_bfloat16 g_Kb[(size_t)BHh * Sq * Dd];   // 32 MB
__device__ __nv_bfloat16 g_Vb[(size_t)BHh * Sq * Dd];   // 32 MB
__device__ float         g_S [(size_t)BHh * Sq * Sq];   // 256 MB fp32 scores
__device__ __nv_bfloat16 g_Pb[(size_t)BHh * Sq * Sq];   // 128 MB bf16 probs
__device__ __nv_bfloat16 g_Cb[(size_t)Mrows * HDc];     // 32 MB concat

// ---------------------------------------------------------------------------
// BF16 mma.sync m16n8k16 GEMM: 128x128 tile, BK=64 (bf16), 256 threads.
// Smem holds bf16 PAIRS in uint32 words; the pair-index math is identical to
// the R4 TF32 kernel (pads AS_LD=36 / BS_LD=136 keep frag reads conflict-free).
// Warp grid 4(M) x 2(N); warp tile 32x64 = 2 x 8 frags of m16n8k16.
// MODE 0: QKV proj  C = X@W[h] + bias -> bf16 Q/K/V  (z = t*8+h)   A fp32, B fp32
// MODE 1: scores    C = Q@K^T * scale -> fp32 g_S     (z = bh)      A bf16, B bf16 trans
// MODE 2: P@V       C -> bf16 concat                  (z = bh)      A bf16, B bf16
// MODE 3: out proj  C = concat@Wo + bo + x -> d_out                 A bf16, B fp32
// Scores & softmax stay fp32; accumulation always fp32.
// ---------------------------------------------------------------------------
#define BM 128
#define BN 128
#define BKF 64        // K per tile in bf16 elements
#define BKP 32        // K per tile in bf16x2 pairs (uint32 words)
#define AS_LD 36      // pair-row pitch: frag-read bank = gid*4+tig, conflict-free
#define BS_LD 136     // pair-row pitch: frag-read bank = tig*8+gid, conflict-free

__device__ __forceinline__ uint32_t packbf(float lo, float hi) {
    uint32_t r;
    asm("cvt.rn.bf16x2.f32 %0, %1, %2;" : "=r"(r) : "f"(hi), "f"(lo));
    return r;
}

__device__ __forceinline__ void mma_bf16(float* d, const uint32_t* a, const uint32_t* b) {
    asm volatile(
        "mma.sync.aligned.m16n8k16.row.col.f32.bf16.bf16.f32 "
        "{%0,%1,%2,%3}, {%4,%5,%6,%7}, {%8,%9}, {%0,%1,%2,%3};"
        : "+f"(d[0]), "+f"(d[1]), "+f"(d[2]), "+f"(d[3])
        : "r"(a[0]), "r"(a[1]), "r"(a[2]), "r"(a[3]), "r"(b[0]), "r"(b[1]));
}

template <int MODE>
__global__ void __launch_bounds__(256, 2) gemm_k(
    const float* __restrict__ X,
    const float* __restrict__ Wq, const float* __restrict__ Wk,
    const float* __restrict__ Wv,
    const float* __restrict__ bq, const float* __restrict__ bk,
    const float* __restrict__ bv,
    const float* __restrict__ Wo, const float* __restrict__ bo,
    float* __restrict__ OUT)
{
    __shared__ uint32_t As[BM * AS_LD];   // [m][kp] pairs
    __shared__ uint32_t Bs[BKP * BS_LD];  // [kp][n] pairs (k-pair packed per n)

    const int tid  = threadIdx.x;
    const int lane = tid & 31;
    const int warp = tid >> 5;
    const int wm   = warp & 3;            // 0..3  (32 rows each)
    const int wn   = warp >> 2;           // 0..1  (64 cols each)
    const int gid  = lane >> 2;           // 0..7
    const int tig  = lane & 3;            // 0..3

    const int n0 = blockIdx.x * BN;
    const int m0 = blockIdx.y * BM;
    const int z  = blockIdx.z;

    // Source pointers
    const float* Afp = nullptr;  const __nv_bfloat16* Abf = nullptr;  int ldA;
    const float* Bfp = nullptr;  const __nv_bfloat16* Bbf = nullptr;
    int Kdim;

    if (MODE == 0) {
        const int t = z >> 3, h = z & 7;
        Afp = X;  ldA = Dd;  Kdim = Dd;
        Bfp = (t == 0 ? Wq : (t == 1 ? Wk : Wv)) + (size_t)h * Dd * Dd;
    } else if (MODE == 1) {
        Abf = g_Qb + (size_t)z * Sq * Dd;  ldA = Dd;  Kdim = Dd;
        Bbf = g_Kb + (size_t)z * Sq * Dd;              // transposed source [n][k]
    } else if (MODE == 2) {
        Abf = g_Pb + (size_t)z * Sq * Sq;  ldA = Sq;  Kdim = Sq;
        Bbf = g_Vb + (size_t)z * Sq * Dd;              // row-major [k][n]
    } else {
        Abf = g_Cb;  ldA = HDc;  Kdim = HDc;
        Bfp = Wo;
    }
    const int ldbN = Dd;   // every B matrix has n-row stride 512

    // Load mappings
    const int a_r = tid >> 1;            // 0..127
    const int a_h = tid & 1;             // half of the 64-k span (32 bf16 each)
    const int b_kp = tid >> 3;           // 0..31 (pair row)
    const int b_nb = (tid & 7) * 16;     // 0..112
    const int t_n  = tid >> 1;           // MODE1: n row 0..127
    const int t_h  = tid & 1;            // MODE1: k half

    float acc[2][8][4];
#pragma unroll
    for (int mi = 0; mi < 2; mi++)
#pragma unroll
        for (int nj = 0; nj < 8; nj++)
#pragma unroll
            for (int e = 0; e < 4; e++) acc[mi][nj][e] = 0.0f;

    for (int k0 = 0; k0 < Kdim; k0 += BKF) {
        // ---- A tile ----
        if (MODE == 0) {
            // fp32 -> bf16x2 pack; 8 float4 per thread
#pragma unroll
            for (int i = 0; i < 8; i++) {
                const float4 av = *(const float4*)(Afp + (size_t)(m0 + a_r) * ldA + k0 + a_h * 32 + 4 * i);
                uint32_t* d = &As[a_r * AS_LD + a_h * 16 + 2 * i];
                d[0] = packbf(av.x, av.y);
                d[1] = packbf(av.z, av.w);
            }
        } else {
            // bf16 direct copy: 4 uint4 per thread (pairs already adjacent)
            const uint4* src = (const uint4*)(Abf + (size_t)(m0 + a_r) * ldA + k0 + a_h * 32);
            uint4* dst = (uint4*)&As[a_r * AS_LD + a_h * 16];
#pragma unroll
            for (int u = 0; u < 4; u++) dst[u] = src[u];
        }
        // ---- B tile ----
        if (MODE == 0 || MODE == 3) {
            // fp32 row-major [k][n]: pack rows 2kp,2kp+1
            const float* r0 = Bfp + (size_t)(k0 + 2 * b_kp) * ldbN + n0 + b_nb;
            const float* r1 = r0 + ldbN;
#pragma unroll
            for (int j = 0; j < 4; j++) {
                const float4 x0 = ((const float4*)r0)[j];
                const float4 x1 = ((const float4*)r1)[j];
                uint32_t* d = &Bs[b_kp * BS_LD + b_nb + 4 * j];
                d[0] = packbf(x0.x, x1.x);
                d[1] = packbf(x0.y, x1.y);
                d[2] = packbf(x0.z, x1.z);
                d[3] = packbf(x0.w, x1.w);
            }
        } else if (MODE == 1) {
            // bf16 transposed source [n][k]: pairs contiguous along k
            const uint4* src = (const uint4*)(Bbf + (size_t)(n0 + t_n) * ldbN + k0 + t_h * 32);
#pragma unroll
            for (int u = 0; u < 4; u++) {
                const uint4 q = src[u];
                const int kp = t_h * 16 + 4 * u;
                Bs[(kp + 0) * BS_LD + t_n] = q.x;
                Bs[(kp + 1) * BS_LD + t_n] = q.y;
                Bs[(kp + 2) * BS_LD + t_n] = q.z;
                Bs[(kp + 3) * BS_LD + t_n] = q.w;
            }
        } else {
            // bf16 row-major [k][n]: interleave rows 2kp,2kp+1 via byte_perm
            const uint4* r0 = (const uint4*)(Bbf + (size_t)(k0 + 2 * b_kp) * ldbN + n0 + b_nb);
            const uint4* r1 = (const uint4*)(Bbf + (size_t)(k0 + 2 * b_kp + 1) * ldbN + n0 + b_nb);
#pragma unroll
            for (int j = 0; j < 2; j++) {
                const uint4 A4 = r0[j];
                const uint4 B4 = r1[j];
                uint32_t* d = &Bs[b_kp * BS_LD + b_nb + 8 * j];
                d[0] = __byte_perm(A4.x, B4.x, 0x5410);
                d[1] = __byte_perm(A4.x, B4.x, 0x7632);
                d[2] = __byte_perm(A4.y, B4.y, 0x5410);
                d[3] = __byte_perm(A4.y, B4.y, 0x7632);
                d[4] = __byte_perm(A4.z, B4.z, 0x5410);
                d[5] = __byte_perm(A4.z, B4.z, 0x7632);
                d[6] = __byte_perm(A4.w, B4.w, 0x5410);
                d[7] = __byte_perm(A4.w, B4.w, 0x7632);
            }
        }
        __syncthreads();

#pragma unroll
        for (int ks = 0; ks < 4; ks++) {          // 4 x k16 steps
            const int kb = ks * 8;                 // pair offset
            uint32_t a[2][4];
#pragma unroll
            for (int mi = 0; mi < 2; mi++) {
                const int r = wm * 32 + mi * 16 + gid;
                a[mi][0] = As[r * AS_LD + kb + tig];
                a[mi][1] = As[(r + 8) * AS_LD + kb + tig];
                a[mi][2] = As[r * AS_LD + kb + tig + 4];
                a[mi][3] = As[(r + 8) * AS_LD + kb + tig + 4];
            }
            uint32_t b[8][2];
#pragma unroll
            for (int nj = 0; nj < 8; nj++) {
                const int c = wn * 64 + nj * 8 + gid;
                b[nj][0] = Bs[(kb + tig) * BS_LD + c];
                b[nj][1] = Bs[(kb + tig + 4) * BS_LD + c];
            }
#pragma unroll
            for (int mi = 0; mi < 2; mi++)
#pragma unroll
                for (int nj = 0; nj < 8; nj++)
                    mma_bf16(acc[mi][nj], a[mi], b[nj]);
        }
        __syncthreads();
    }

    // ---- epilogue ----
#pragma unroll
    for (int mi = 0; mi < 2; mi++) {
#pragma unroll
        for (int nj = 0; nj < 8; nj++) {
            const int rr0 = wm * 32 + mi * 16 + gid;
            const int rr1 = rr0 + 8;
            const int cc0 = wn * 64 + nj * 8 + 2 * tig;
            const float* a4 = acc[mi][nj];

            if (MODE == 0) {
                const int t = z >> 3, h = z & 7;
                const float* bias = (t == 0 ? bq : (t == 1 ? bk : bv)) + h * Dd;
                __nv_bfloat16* Cb = (t == 0 ? g_Qb : (t == 1 ? g_Kb : g_Vb));
                const int b = m0 >> 11;
                const int sb = (m0 & (Sq - 1));
                __nv_bfloat16* Cp = Cb + (size_t)(b * Hh + h) * Sq * Dd;
                const int c0 = n0 + cc0;
                const float bias0 = bias[c0], bias1 = bias[c0 + 1];
                *(uint32_t*)&Cp[(size_t)(sb + rr0) * Dd + c0] = packbf(a4[0] + bias0, a4[1] + bias1);
                *(uint32_t*)&Cp[(size_t)(sb + rr1) * Dd + c0] = packbf(a4[2] + bias0, a4[3] + bias1);
            } else if (MODE == 1) {
                float* Cp = g_S + (size_t)z * Sq * Sq;
                const int c0 = n0 + cc0;
                Cp[(size_t)(m0 + rr0) * Sq + c0]     = a4[0] * SCALE;
                Cp[(size_t)(m0 + rr0) * Sq + c0 + 1] = a4[1] * SCALE;
                Cp[(size_t)(m0 + rr1) * Sq + c0]     = a4[2] * SCALE;
                Cp[(size_t)(m0 + rr1) * Sq + c0 + 1] = a4[3] * SCALE;
            } else if (MODE == 2) {
                const int b = z >> 3, h = z & 7;
                const int c0 = h * Dd + n0 + cc0;
                *(uint32_t*)&g_Cb[(size_t)(b * Sq + m0 + rr0) * HDc + c0] = packbf(a4[0], a4[1]);
                *(uint32_t*)&g_Cb[(size_t)(b * Sq + m0 + rr1) * HDc + c0] = packbf(a4[2], a4[3]);
            } else {
                const int r0 = m0 + rr0, r1 = m0 + rr1;
                const int c0 = n0 + cc0;
                const float bo0 = bo[c0], bo1 = bo[c0 + 1];
                OUT[(size_t)r0 * Dd + c0]     = a4[0] + bo0 + X[(size_t)r0 * Dd + c0];
                OUT[(size_t)r0 * Dd + c0 + 1] = a4[1] + bo1 + X[(size_t)r0 * Dd + c0 + 1];
                OUT[(size_t)r1 * Dd + c0]     = a4[2] + bo0 + X[(size_t)r1 * Dd + c0];
                OUT[(size_t)r1 * Dd + c0 + 1] = a4[3] + bo1 + X[(size_t)r1 * Dd + c0 + 1];
            }
        }
    }
}

// ---------------------------------------------------------------------------
// Row softmax: fp32 scores in g_S -> bf16 probs in g_Pb.
// 32768 rows x 2048 cols, one 256-thread block per row.
// ---------------------------------------------------------------------------
__global__ void __launch_bounds__(256) softmax_k()
{
    const int row = blockIdx.x;
    const float* p = g_S + (size_t)row * Sq;
    __nv_bfloat16* po = g_Pb + (size_t)row * Sq;
    const int tid = threadIdx.x;

    float v[8];
    float mx = -1e30f;
#pragma unroll
    for (int i = 0; i < 8; i++) {
        v[i] = p[tid + i * 256];
        mx = fmaxf(mx, v[i]);
    }
#pragma unroll
    for (int o = 16; o; o >>= 1) mx = fmaxf(mx, __shfl_xor_sync(0xFFFFFFFFu, mx, o));

    __shared__ float red[8];
    const int w = tid >> 5, l = tid & 31;
    if (l == 0) red[w] = mx;
    __syncthreads();
    float m = red[0];
#pragma unroll
    for (int i = 1; i < 8; i++) m = fmaxf(m, red[i]);
    __syncthreads();

    float s = 0.0f;
#pragma unroll
    for (int i = 0; i < 8; i++) {
        v[i] = __expf(v[i] - m);
        s += v[i];
    }
#pragma unroll
    for (int o = 16; o; o >>= 1) s += __shfl_xor_sync(0xFFFFFFFFu, s, o);
    if (l == 0) red[w] = s;
    __syncthreads();
    float tot = 0.0f;
#pragma unroll
    for (int i = 0; i < 8; i++) tot += red[i];
    const float inv = __frcp_rn(tot);

#pragma unroll
    for (int i = 0; i < 8; i++) po[tid + i * 256] = __float2bfloat16(v[i] * inv);
}

// ---------------------------------------------------------------------------
extern "C" void kernel_launch(void* const* d_in, const int* in_sizes, int n_in,
                              void* d_out, int out_size)
{
    (void)in_sizes; (void)n_in; (void)out_size;
    const float* x  = (const float*)d_in[0];
    const float* Wq = (const float*)d_in[1];
    const float* Wk = (const float*)d_in[2];
    const float* Wv = (const float*)d_in[3];
    const float* bq = (const float*)d_in[4];
    const float* bk = (const float*)d_in[5];
    const float* bv = (const float*)d_in[6];
    const float* Wo = (const float*)d_in[7];
    const float* bo = (const float*)d_in[8];
    float* out = (float*)d_out;

    // 1) QKV projections: 24 GEMMs of [4096,512]x[512,512] -> bf16
    gemm_k<0><<<dim3(Dd / BN, Mrows / BM, 24), 256>>>(x, Wq, Wk, Wv, bq, bk, bv, Wo, bo, out);
    // 2) Scores: 16 GEMMs of [2048,2048,512] -> fp32, scaled
    gemm_k<1><<<dim3(Sq / BN, Sq / BM, BHh), 256>>>(x, Wq, Wk, Wv, bq, bk, bv, Wo, bo, out);
    // 3) Row softmax fp32 -> bf16 probs
    softmax_k<<<BHh * Sq, 256>>>();
    // 4) P @ V -> bf16 concat: 16 GEMMs of [2048,512,2048]
    gemm_k<2><<<dim3(Dd / BN, Sq / BM, BHh), 256>>>(x, Wq, Wk, Wv, bq, bk, bv, Wo, bo, out);
    // 5) Output projection + bias + residual: [4096,512,4096] -> fp32 out
    gemm_k<3><<<dim3(Dd / BN, Mrows / BM, 1), 256>>>(x, Wq, Wk, Wv, bq, bk, bv, Wo, bo, out);
}